// round 15
// baseline (speedup 1.0000x reference)
#include <cuda_runtime.h>
#include <math.h>

#define NN 20000
#define NE 640000
#define D  128

// ---------------- static device scratch ----------------
__device__ float g_qhat[NN * D];
__device__ float g_agg[NN * D];
__device__ float g_exp[NE];
__device__ int   g_eids[NE];
__device__ int   g_deg[NN];
__device__ int   g_off[NN + 1];
__device__ int   g_cur[NN];
__device__ float g_WoT[D * D];       // Wo^T
// tf32 hi/lo split of combined weights, n-major [n*128 + k]
__device__ float g_WcH[D * D], g_WcL[D * D];
__device__ float g_W2H[D * D], g_W2L[D * D];

// ---------------- tf32 helpers ----------------
__device__ __forceinline__ unsigned tf32_hi(float a) {
    unsigned h;
    asm("cvt.rna.tf32.f32 %0, %1;" : "=r"(h) : "f"(a));
    return h;
}

#define MMA_TF32(c, a0, a1, a2, a3, b0, b1)                                    \
    asm("mma.sync.aligned.m16n8k8.row.col.f32.tf32.tf32.f32 "                  \
        "{%0,%1,%2,%3}, {%4,%5,%6,%7}, {%8,%9}, {%0,%1,%2,%3};"                \
        : "+f"(c[0]), "+f"(c[1]), "+f"(c[2]), "+f"(c[3])                       \
        : "r"(a0), "r"(a1), "r"(a2), "r"(a3), "r"(b0), "r"(b1))

// ---------------- B-chain: zero counters ----------------
__global__ void zero_kernel() {
    int i = blockIdx.x * 1024 + threadIdx.x;
    if (i < NN) { g_deg[i] = 0; g_cur[i] = 0; }
}

// ---------------- B-chain: degree histogram ----------------
__global__ void deg_kernel(const int* __restrict__ tgt) {
    int i = (blockIdx.x * 256 + threadIdx.x) * 4;
    if (i >= NE) return;
    int4 t = *reinterpret_cast<const int4*>(tgt + i);
    atomicAdd(&g_deg[t.x], 1);
    atomicAdd(&g_deg[t.y], 1);
    atomicAdd(&g_deg[t.z], 1);
    atomicAdd(&g_deg[t.w], 1);
}

// ---------------- B-chain: single-block scan ----------------
__global__ void scan_kernel() {
    const int PER = (NN + 1023) / 1024;          // 20
    int t = threadIdx.x;
    int lane = t & 31, wid = t >> 5;
    int base = t * PER;

    int local[PER];
    int s = 0;
#pragma unroll
    for (int j = 0; j < PER; j++) {
        int idx = base + j;
        int v = (idx < NN) ? g_deg[idx] : 0;
        local[j] = s;
        s += v;
    }
    int incl = s;
#pragma unroll
    for (int o = 1; o < 32; o <<= 1) {
        int u = __shfl_up_sync(0xffffffffu, incl, o);
        if (lane >= o) incl += u;
    }
    __shared__ int wsum[32];
    if (lane == 31) wsum[wid] = incl;
    __syncthreads();
    if (wid == 0) {
        int v = wsum[lane];
        int wv = v;
#pragma unroll
        for (int o = 1; o < 32; o <<= 1) {
            int u = __shfl_up_sync(0xffffffffu, wv, o);
            if (lane >= o) wv += u;
        }
        wsum[lane] = wv - v;
    }
    __syncthreads();
    int excl = incl - s + wsum[wid];
#pragma unroll
    for (int j = 0; j < PER; j++) {
        int idx = base + j;
        if (idx < NN) g_off[idx] = excl + local[j];
    }
    if (t == 1023) g_off[NN] = excl + s;
}

// ---------------- A-chain: transpose Wo ----------------
__global__ void transpose_kernel(const float* __restrict__ Wo) {
    __shared__ float tile[32][33];
    int ti = blockIdx.x;
    int bx = ti & 3, by = ti >> 2;
    int tx = threadIdx.x & 31, ty = threadIdx.x >> 5;
    tile[ty][tx] = Wo[(by * 32 + ty) * D + bx * 32 + tx];
    __syncthreads();
    g_WoT[(bx * 32 + ty) * D + by * 32 + tx] = tile[tx][ty];
}

// ---------------- A-chain: combine weights (tf32 split, n-major) ----------------
__global__ void combine_kernel(const float* __restrict__ Wq,
                               const float* __restrict__ Wk,
                               const float* __restrict__ Wv) {
    int w = (blockIdx.x * 256 + threadIdx.x) >> 5;
    int lane = threadIdx.x & 31;
    int mat = w >> 14;
    int a   = (w >> 7) & 127;   // k index
    int b   = w & 127;          // n index
    float4 x, y;
    if (mat == 0) {
        x = reinterpret_cast<const float4*>(Wq)[a * 32 + lane];
        y = reinterpret_cast<const float4*>(Wk)[b * 32 + lane];
    } else {
        x = reinterpret_cast<const float4*>(Wv)[a * 32 + lane];
        y = reinterpret_cast<const float4*>(g_WoT)[b * 32 + lane];
    }
    float c = x.x * y.x + x.y * y.y + x.z * y.z + x.w * y.w;
#pragma unroll
    for (int o = 16; o; o >>= 1) c += __shfl_xor_sync(0xffffffffu, c, o);
    if (lane == 0) {
        unsigned h = tf32_hi(c);
        float lo = c - __uint_as_float(h);
        if (mat == 0) {
            g_WcH[b * D + a] = __uint_as_float(h);
            g_WcL[b * D + a] = __uint_as_float(tf32_hi(lo));
        } else {
            g_W2H[b * D + a] = __uint_as_float(h);
            g_W2L[b * D + a] = __uint_as_float(tf32_hi(lo));
        }
    }
}

// ================ 3xTF32 GEMM: 64x128 tile, 256 thr, 8 warps ===============
#define SMEM_GEMM_BYTES ((64 + 128 + 128) * 36 * 4)   // 46080

#define TF32_GEMM_MAINLOOP(Aptr, BHsym, BLsym)                                 \
    extern __shared__ float sm[];                                              \
    float* As = sm;                                                            \
    float* Bh = sm + 64 * 36;                                                  \
    float* Bl = sm + (64 + 128) * 36;                                          \
    int t  = threadIdx.x;                                                      \
    int rb = blockIdx.x * 64;                                                  \
    int w = t >> 5, lane = t & 31;                                             \
    int wm = w >> 1, wn = w & 1;                                               \
    int qid = lane >> 2, tq = lane & 3;                                        \
    int ra = wm * 16 + qid;                                                    \
    float acc[8][4];                                                           \
    _Pragma("unroll")                                                          \
    for (int nt = 0; nt < 8; nt++)                                             \
        acc[nt][0] = acc[nt][1] = acc[nt][2] = acc[nt][3] = 0.f;               \
    const float4* A4  = reinterpret_cast<const float4*>(Aptr);                 \
    const float4* BH4 = reinterpret_cast<const float4*>(BHsym);                \
    const float4* BL4 = reinterpret_cast<const float4*>(BLsym);                \
    for (int kt = 0; kt < 4; kt++) {                                           \
        __syncthreads();                                                       \
        _Pragma("unroll")                                                      \
        for (int i = 0; i < 2; i++) {                                          \
            int lin = i * 256 + t;                                             \
            int r = lin >> 3, c4 = lin & 7;                                    \
            float4 v = make_float4(0.f, 0.f, 0.f, 0.f);                        \
            if (rb + r < NN) v = A4[(size_t)(rb + r) * 32 + kt * 8 + c4];      \
            *reinterpret_cast<float4*>(&As[r * 36 + c4 * 4]) = v;              \
        }                                                                      \
        _Pragma("unroll")                                                      \
        for (int i = 0; i < 4; i++) {                                          \
            int lin = i * 256 + t;                                             \
            int r = lin >> 3, c4 = lin & 7;                                    \
            *reinterpret_cast<float4*>(&Bh[r * 36 + c4 * 4]) =                 \
                BH4[r * 32 + kt * 8 + c4];                                     \
            *reinterpret_cast<float4*>(&Bl[r * 36 + c4 * 4]) =                 \
                BL4[r * 32 + kt * 8 + c4];                                     \
        }                                                                      \
        __syncthreads();                                                       \
        _Pragma("unroll")                                                      \
        for (int k8 = 0; k8 < 4; k8++) {                                       \
            int k0 = k8 * 8;                                                   \
            float a0f = As[ra * 36 + k0 + tq];                                 \
            float a1f = As[(ra + 8) * 36 + k0 + tq];                           \
            float a2f = As[ra * 36 + k0 + 4 + tq];                             \
            float a3f = As[(ra + 8) * 36 + k0 + 4 + tq];                       \
            unsigned ah0 = tf32_hi(a0f), ah1 = tf32_hi(a1f);                   \
            unsigned ah2 = tf32_hi(a2f), ah3 = tf32_hi(a3f);                   \
            unsigned al0 = tf32_hi(a0f - __uint_as_float(ah0));                \
            unsigned al1 = tf32_hi(a1f - __uint_as_float(ah1));                \
            unsigned al2 = tf32_hi(a2f - __uint_as_float(ah2));                \
            unsigned al3 = tf32_hi(a3f - __uint_as_float(ah3));                \
            _Pragma("unroll")                                                  \
            for (int nt = 0; nt < 8; nt++) {                                   \
                int nb = (wn * 64 + nt * 8 + qid) * 36 + k0 + tq;              \
                unsigned bh0 = __float_as_uint(Bh[nb]);                        \
                unsigned bh1 = __float_as_uint(Bh[nb + 4]);                    \
                unsigned bl0 = __float_as_uint(Bl[nb]);                        \
                unsigned bl1 = __float_as_uint(Bl[nb + 4]);                    \
                MMA_TF32(acc[nt], al0, al1, al2, al3, bh0, bh1);               \
                MMA_TF32(acc[nt], ah0, ah1, ah2, ah3, bl0, bl1);               \
                MMA_TF32(acc[nt], ah0, ah1, ah2, ah3, bh0, bh1);               \
            }                                                                  \
        }                                                                      \
    }

// gemm1: qhat = query_node @ Wc
__global__ __launch_bounds__(256, 4) void gemm_qhat_kernel(const float* __restrict__ A) {
    TF32_GEMM_MAINLOOP(A, g_WcH, g_WcL)
    int r0 = rb + ra, r1 = r0 + 8;
#pragma unroll
    for (int nt = 0; nt < 8; nt++) {
        int col = wn * 64 + nt * 8 + 2 * tq;
        if (r0 < NN)
            *reinterpret_cast<float2*>(&g_qhat[(size_t)r0 * D + col]) =
                make_float2(acc[nt][0], acc[nt][1]);
        if (r1 < NN)
            *reinterpret_cast<float2*>(&g_qhat[(size_t)r1 * D + col]) =
                make_float2(acc[nt][2], acc[nt][3]);
    }
}

// gemm2 + bias + LayerNorm
__global__ __launch_bounds__(256, 4) void gemm_ln_kernel(const float* __restrict__ bo,
                                                         const float* __restrict__ gamma,
                                                         const float* __restrict__ beta,
                                                         float* __restrict__ out) {
    TF32_GEMM_MAINLOOP(g_agg, g_W2H, g_W2L)
#pragma unroll
    for (int nt = 0; nt < 8; nt++) {
        int col = wn * 64 + nt * 8 + 2 * tq;
        float2 b2 = *reinterpret_cast<const float2*>(&bo[col]);
        acc[nt][0] += b2.x; acc[nt][1] += b2.y;
        acc[nt][2] += b2.x; acc[nt][3] += b2.y;
    }
    float s0 = 0.f, s1 = 0.f, q0 = 0.f, q1 = 0.f;
#pragma unroll
    for (int nt = 0; nt < 8; nt++) {
        s0 += acc[nt][0] + acc[nt][1];
        s1 += acc[nt][2] + acc[nt][3];
        q0 += acc[nt][0] * acc[nt][0] + acc[nt][1] * acc[nt][1];
        q1 += acc[nt][2] * acc[nt][2] + acc[nt][3] * acc[nt][3];
    }
#pragma unroll
    for (int o = 1; o <= 2; o <<= 1) {
        s0 += __shfl_xor_sync(0xffffffffu, s0, o);
        s1 += __shfl_xor_sync(0xffffffffu, s1, o);
        q0 += __shfl_xor_sync(0xffffffffu, q0, o);
        q1 += __shfl_xor_sync(0xffffffffu, q1, o);
    }
    float* red_s = As;
    float* red_q = As + 128;
    __syncthreads();
    if (tq == 0) {
        int row0 = wm * 16 + qid;
        red_s[wn * 64 + row0]     = s0;
        red_s[wn * 64 + row0 + 8] = s1;
        red_q[wn * 64 + row0]     = q0;
        red_q[wn * 64 + row0 + 8] = q1;
    }
    __syncthreads();
    int row0 = wm * 16 + qid, row1 = row0 + 8;
    float st0 = red_s[row0] + red_s[64 + row0];
    float st1 = red_s[row1] + red_s[64 + row1];
    float qt0 = red_q[row0] + red_q[64 + row0];
    float qt1 = red_q[row1] + red_q[64 + row1];
    float mu0 = st0 * (1.f / 128.f), mu1 = st1 * (1.f / 128.f);
    float var0 = qt0 * (1.f / 128.f) - mu0 * mu0;
    float var1 = qt1 * (1.f / 128.f) - mu1 * mu1;
    float rs0 = rsqrtf(var0 + 1e-5f);
    float rs1 = rsqrtf(var1 + 1e-5f);

    int r0 = rb + ra, r1 = r0 + 8;
#pragma unroll
    for (int nt = 0; nt < 8; nt++) {
        int col = wn * 64 + nt * 8 + 2 * tq;
        float2 g2  = *reinterpret_cast<const float2*>(&gamma[col]);
        float2 be2 = *reinterpret_cast<const float2*>(&beta[col]);
        if (r0 < NN)
            *reinterpret_cast<float2*>(&out[(size_t)r0 * D + col]) =
                make_float2((acc[nt][0] - mu0) * rs0 * g2.x + be2.x,
                            (acc[nt][1] - mu0) * rs0 * g2.y + be2.y);
        if (r1 < NN)
            *reinterpret_cast<float2*>(&out[(size_t)r1 * D + col]) =
                make_float2((acc[nt][2] - mu1) * rs1 * g2.x + be2.x,
                            (acc[nt][3] - mu1) * rs1 * g2.y + be2.y);
    }
}

// ---------------- scores: warp per 8 edges; CSR-ordered exp + eids ----------------
__global__ void scores_kernel(const float* __restrict__ key_edge,
                              const int* __restrict__ tgt) {
    int w = (blockIdx.x * blockDim.x + threadIdx.x) >> 5;
    int e0 = w * 8;
    if (e0 >= NE) return;
    int lane = threadIdx.x & 31;

    int4 ta = *reinterpret_cast<const int4*>(tgt + e0);
    int4 tb = *reinterpret_cast<const int4*>(tgt + e0 + 4);
    int t[8] = {ta.x, ta.y, ta.z, ta.w, tb.x, tb.y, tb.z, tb.w};

    const float4* K4 = reinterpret_cast<const float4*>(key_edge);
    const float4* Q4 = reinterpret_cast<const float4*>(g_qhat);

    float4 kv[8], qv[8];
#pragma unroll
    for (int j = 0; j < 8; j++) kv[j] = __ldcs(&K4[(size_t)(e0 + j) * 32 + lane]);
#pragma unroll
    for (int j = 0; j < 8; j++) qv[j] = Q4[(size_t)t[j] * 32 + lane];

    float d[8];
#pragma unroll
    for (int j = 0; j < 8; j++)
        d[j] = kv[j].x * qv[j].x + kv[j].y * qv[j].y + kv[j].z * qv[j].z + kv[j].w * qv[j].w;
#pragma unroll
    for (int o = 16; o; o >>= 1) {
#pragma unroll
        for (int j = 0; j < 8; j++) d[j] += __shfl_xor_sync(0xffffffffu, d[j], o);
    }
    if (lane < 8) {
        float ds; int ts;
#pragma unroll
        for (int j = 0; j < 8; j++) if (lane == j) { ds = d[j]; ts = t[j]; }
        float sc = ds * 0.08838834764831845f;   // 128^-0.5
        float ex = expf(sc);                    // scores ~ N(0,1): safe without max-shift
        int p = g_off[ts] + atomicAdd(&g_cur[ts], 1);
        g_eids[p] = e0 + lane;
        g_exp[p]  = ex;
    }
}

// ---------------- node: single-pass aggregation + late normalize ----------------
__global__ void node_kernel(const float* __restrict__ value,
                            float* __restrict__ attn_out) {
    int n = (blockIdx.x << 3) + (threadIdx.x >> 5);
    if (n >= NN) return;
    int lane = threadIdx.x & 31;
    int s0 = g_off[n], s1 = g_off[n + 1];

    const float4* V4 = reinterpret_cast<const float4*>(value);
    float ss = 0.f;
    float4 acc = make_float4(0.f, 0.f, 0.f, 0.f);

    int i = s0;
    for (; i + 8 <= s1; i += 8) {
        int   e[8];
        float wgt[8];
        float4 v[8];
#pragma unroll
        for (int j = 0; j < 8; j++) e[j] = g_eids[i + j];
#pragma unroll
        for (int j = 0; j < 8; j++) wgt[j] = g_exp[i + j];
#pragma unroll
        for (int j = 0; j < 8; j++) v[j] = __ldcs(&V4[(size_t)e[j] * 32 + lane]);
#pragma unroll
        for (int j = 0; j < 8; j++) {
            ss += wgt[j];
            acc.x = fmaf(wgt[j], v[j].x, acc.x);
            acc.y = fmaf(wgt[j], v[j].y, acc.y);
            acc.z = fmaf(wgt[j], v[j].z, acc.z);
            acc.w = fmaf(wgt[j], v[j].w, acc.w);
        }
    }
    for (; i < s1; i++) {
        int e = g_eids[i];
        float w = g_exp[i];
        ss += w;
        float4 v = __ldcs(&V4[(size_t)e * 32 + lane]);
        acc.x = fmaf(w, v.x, acc.x); acc.y = fmaf(w, v.y, acc.y);
        acc.z = fmaf(w, v.z, acc.z); acc.w = fmaf(w, v.w, acc.w);
    }
    float inv = 1.f / (ss + 1e-12f);
    acc.x *= inv; acc.y *= inv; acc.z *= inv; acc.w *= inv;
    reinterpret_cast<float4*>(g_agg)[(size_t)n * 32 + lane] = acc;

    if (attn_out) {
        for (int k = s0 + lane; k < s1; k += 32)
            attn_out[g_eids[k]] = g_exp[k] * inv;
    }
}

// ---------------- launch (two-stream DAG) ----------------
extern "C" void kernel_launch(void* const* d_in, const int* in_sizes, int n_in,
                              void* d_out, int out_size) {
    const float* qn    = (const float*)d_in[0];
    const float* ke    = (const float*)d_in[1];
    const float* ve    = (const float*)d_in[2];
    const int*   ei    = (const int*)  d_in[3];
    const float* Wq    = (const float*)d_in[4];
    const float* Wk    = (const float*)d_in[5];
    const float* Wv    = (const float*)d_in[6];
    const float* Wo    = (const float*)d_in[7];
    const float* bo    = (const float*)d_in[8];
    const float* gamma = (const float*)d_in[9];
    const float* beta  = (const float*)d_in[10];

    const int* tgt = ei + NE;
    float* out = (float*)d_out;
    float* attn = (out_size >= NN * D + NE) ? (out + NN * D) : nullptr;

    static int inited = 0;
    static cudaStream_t sB;
    static cudaEvent_t evFork, evJoin;
    if (!inited) {
        cudaFuncSetAttribute(gemm_qhat_kernel,
                             cudaFuncAttributeMaxDynamicSharedMemorySize, SMEM_GEMM_BYTES);
        cudaFuncSetAttribute(gemm_ln_kernel,
                             cudaFuncAttributeMaxDynamicSharedMemorySize, SMEM_GEMM_BYTES);
        cudaStreamCreateWithFlags(&sB, cudaStreamNonBlocking);
        cudaEventCreateWithFlags(&evFork, cudaEventDisableTiming);
        cudaEventCreateWithFlags(&evJoin, cudaEventDisableTiming);
        inited = 1;
    }

    // fork: B-chain (CSR build) runs under the A-chain's shadow
    cudaEventRecord(evFork, 0);
    cudaStreamWaitEvent(sB, evFork, 0);
    zero_kernel<<<20, 1024, 0, sB>>>();
    deg_kernel<<<625, 256, 0, sB>>>(tgt);
    scan_kernel<<<1, 1024, 0, sB>>>();
    cudaEventRecord(evJoin, sB);

    // A-chain: weights -> gemm1
    transpose_kernel<<<16, 1024>>>(Wo);
    combine_kernel<<<4096, 256>>>(Wq, Wk, Wv);
    gemm_qhat_kernel<<<(NN + 63) / 64, 256, SMEM_GEMM_BYTES>>>(qn);

    // join, then the dependent chain
    cudaStreamWaitEvent(0, evJoin, 0);
    scores_kernel<<<(NE / 8 + 7) / 8, 256>>>(ke, tgt);
    node_kernel<<<(NN + 7) / 8, 256>>>(ve, attn);
    gemm_ln_kernel<<<(NN + 63) / 64, 256, SMEM_GEMM_BYTES>>>(bo, gamma, beta, out);
}

// round 16
// speedup vs baseline: 1.0103x; 1.0103x over previous
#include <cuda_runtime.h>
#include <math.h>

#define NN 20000
#define NE 640000
#define D  128

// ---------------- static device scratch ----------------
__device__ float g_qhat[NN * D];
__device__ float g_agg[NN * D];
__device__ float g_exp[NE];
__device__ int   g_eids[NE];
__device__ int   g_deg[NN];
__device__ int   g_off[NN + 1];
__device__ int   g_cur[NN];
__device__ float g_WoT[D * D];       // Wo^T
// tf32 hi/lo split of combined weights, n-major [n*128 + k]
__device__ float g_WcH[D * D], g_WcL[D * D];
__device__ float g_W2H[D * D], g_W2L[D * D];

// ---------------- tf32 helpers ----------------
__device__ __forceinline__ unsigned tf32_hi(float a) {
    unsigned h;
    asm("cvt.rna.tf32.f32 %0, %1;" : "=r"(h) : "f"(a));
    return h;
}

#define MMA_TF32(c, a0, a1, a2, a3, b0, b1)                                    \
    asm("mma.sync.aligned.m16n8k8.row.col.f32.tf32.tf32.f32 "                  \
        "{%0,%1,%2,%3}, {%4,%5,%6,%7}, {%8,%9}, {%0,%1,%2,%3};"                \
        : "+f"(c[0]), "+f"(c[1]), "+f"(c[2]), "+f"(c[3])                       \
        : "r"(a0), "r"(a1), "r"(a2), "r"(a3), "r"(b0), "r"(b1))

// ---------------- B-chain: zero counters ----------------
__global__ void zero_kernel() {
    int i = blockIdx.x * 1024 + threadIdx.x;
    if (i < NN) { g_deg[i] = 0; g_cur[i] = 0; }
}

// ---------------- B-chain: degree histogram ----------------
__global__ void deg_kernel(const int* __restrict__ tgt) {
    int i = (blockIdx.x * 256 + threadIdx.x) * 4;
    if (i >= NE) return;
    int4 t = *reinterpret_cast<const int4*>(tgt + i);
    atomicAdd(&g_deg[t.x], 1);
    atomicAdd(&g_deg[t.y], 1);
    atomicAdd(&g_deg[t.z], 1);
    atomicAdd(&g_deg[t.w], 1);
}

// ---------------- B-chain: single-block scan ----------------
__global__ void scan_kernel() {
    const int PER = (NN + 1023) / 1024;          // 20
    int t = threadIdx.x;
    int lane = t & 31, wid = t >> 5;
    int base = t * PER;

    int local[PER];
    int s = 0;
#pragma unroll
    for (int j = 0; j < PER; j++) {
        int idx = base + j;
        int v = (idx < NN) ? g_deg[idx] : 0;
        local[j] = s;
        s += v;
    }
    int incl = s;
#pragma unroll
    for (int o = 1; o < 32; o <<= 1) {
        int u = __shfl_up_sync(0xffffffffu, incl, o);
        if (lane >= o) incl += u;
    }
    __shared__ int wsum[32];
    if (lane == 31) wsum[wid] = incl;
    __syncthreads();
    if (wid == 0) {
        int v = wsum[lane];
        int wv = v;
#pragma unroll
        for (int o = 1; o < 32; o <<= 1) {
            int u = __shfl_up_sync(0xffffffffu, wv, o);
            if (lane >= o) wv += u;
        }
        wsum[lane] = wv - v;
    }
    __syncthreads();
    int excl = incl - s + wsum[wid];
#pragma unroll
    for (int j = 0; j < PER; j++) {
        int idx = base + j;
        if (idx < NN) g_off[idx] = excl + local[j];
    }
    if (t == 1023) g_off[NN] = excl + s;
}

// ---------------- A-chain: transpose Wo ----------------
__global__ void transpose_kernel(const float* __restrict__ Wo) {
    __shared__ float tile[32][33];
    int ti = blockIdx.x;
    int bx = ti & 3, by = ti >> 2;
    int tx = threadIdx.x & 31, ty = threadIdx.x >> 5;
    tile[ty][tx] = Wo[(by * 32 + ty) * D + bx * 32 + tx];
    __syncthreads();
    g_WoT[(bx * 32 + ty) * D + by * 32 + tx] = tile[tx][ty];
}

// ---------------- A-chain: combine weights (tf32 split, n-major) ----------------
__global__ void combine_kernel(const float* __restrict__ Wq,
                               const float* __restrict__ Wk,
                               const float* __restrict__ Wv) {
    int w = (blockIdx.x * 256 + threadIdx.x) >> 5;
    int lane = threadIdx.x & 31;
    int mat = w >> 14;
    int a   = (w >> 7) & 127;   // k index
    int b   = w & 127;          // n index
    float4 x, y;
    if (mat == 0) {
        x = reinterpret_cast<const float4*>(Wq)[a * 32 + lane];
        y = reinterpret_cast<const float4*>(Wk)[b * 32 + lane];
    } else {
        x = reinterpret_cast<const float4*>(Wv)[a * 32 + lane];
        y = reinterpret_cast<const float4*>(g_WoT)[b * 32 + lane];
    }
    float c = x.x * y.x + x.y * y.y + x.z * y.z + x.w * y.w;
#pragma unroll
    for (int o = 16; o; o >>= 1) c += __shfl_xor_sync(0xffffffffu, c, o);
    if (lane == 0) {
        unsigned h = tf32_hi(c);
        float lo = c - __uint_as_float(h);
        if (mat == 0) {
            g_WcH[b * D + a] = __uint_as_float(h);
            g_WcL[b * D + a] = __uint_as_float(tf32_hi(lo));
        } else {
            g_W2H[b * D + a] = __uint_as_float(h);
            g_W2L[b * D + a] = __uint_as_float(tf32_hi(lo));
        }
    }
}

// ================ gemm1: 64x64 tile, 128 thr, 4 warps (high occupancy) ======
// bid: rb = (bid>>1)*64, cb = bid&1 (which 64-col half). Warp wm owns rows
// [wm*16,+16) x this block's 64 cols. acc[8][4] fp32. smem 27.6 KB.

#define SMEM_G1_BYTES (3 * 64 * 36 * 4)   // 27648

__global__ __launch_bounds__(128, 8) void gemm_qhat_kernel(const float* __restrict__ A) {
    extern __shared__ float sm[];
    float* As = sm;
    float* Bh = sm + 64 * 36;
    float* Bl = sm + 2 * 64 * 36;
    int t  = threadIdx.x;
    int rb = (blockIdx.x >> 1) * 64;
    int cb = blockIdx.x & 1;
    int w = t >> 5, lane = t & 31;
    int qid = lane >> 2, tq = lane & 3;
    int ra = w * 16 + qid;
    float acc[8][4];
#pragma unroll
    for (int nt = 0; nt < 8; nt++)
        acc[nt][0] = acc[nt][1] = acc[nt][2] = acc[nt][3] = 0.f;
    const float4* A4  = reinterpret_cast<const float4*>(A);
    const float4* BH4 = reinterpret_cast<const float4*>(g_WcH);
    const float4* BL4 = reinterpret_cast<const float4*>(g_WcL);
    for (int kt = 0; kt < 4; kt++) {
        __syncthreads();
#pragma unroll
        for (int i = 0; i < 4; i++) {
            int lin = i * 128 + t;
            int r = lin >> 3, c4 = lin & 7;
            float4 v = make_float4(0.f, 0.f, 0.f, 0.f);
            if (rb + r < NN) v = A4[(size_t)(rb + r) * 32 + kt * 8 + c4];
            *reinterpret_cast<float4*>(&As[r * 36 + c4 * 4]) = v;
            *reinterpret_cast<float4*>(&Bh[r * 36 + c4 * 4]) =
                BH4[(cb * 64 + r) * 32 + kt * 8 + c4];
            *reinterpret_cast<float4*>(&Bl[r * 36 + c4 * 4]) =
                BL4[(cb * 64 + r) * 32 + kt * 8 + c4];
        }
        __syncthreads();
#pragma unroll
        for (int k8 = 0; k8 < 4; k8++) {
            int k0 = k8 * 8;
            float a0f = As[ra * 36 + k0 + tq];
            float a1f = As[(ra + 8) * 36 + k0 + tq];
            float a2f = As[ra * 36 + k0 + 4 + tq];
            float a3f = As[(ra + 8) * 36 + k0 + 4 + tq];
            unsigned ah0 = tf32_hi(a0f), ah1 = tf32_hi(a1f);
            unsigned ah2 = tf32_hi(a2f), ah3 = tf32_hi(a3f);
            unsigned al0 = tf32_hi(a0f - __uint_as_float(ah0));
            unsigned al1 = tf32_hi(a1f - __uint_as_float(ah1));
            unsigned al2 = tf32_hi(a2f - __uint_as_float(ah2));
            unsigned al3 = tf32_hi(a3f - __uint_as_float(ah3));
#pragma unroll
            for (int nt = 0; nt < 8; nt++) {
                int nb = (nt * 8 + qid) * 36 + k0 + tq;
                unsigned bh0 = __float_as_uint(Bh[nb]);
                unsigned bh1 = __float_as_uint(Bh[nb + 4]);
                unsigned bl0 = __float_as_uint(Bl[nb]);
                unsigned bl1 = __float_as_uint(Bl[nb + 4]);
                MMA_TF32(acc[nt], al0, al1, al2, al3, bh0, bh1);
                MMA_TF32(acc[nt], ah0, ah1, ah2, ah3, bl0, bl1);
                MMA_TF32(acc[nt], ah0, ah1, ah2, ah3, bh0, bh1);
            }
        }
    }
    int r0 = rb + ra, r1 = r0 + 8;
#pragma unroll
    for (int nt = 0; nt < 8; nt++) {
        int col = cb * 64 + nt * 8 + 2 * tq;
        if (r0 < NN)
            *reinterpret_cast<float2*>(&g_qhat[(size_t)r0 * D + col]) =
                make_float2(acc[nt][0], acc[nt][1]);
        if (r1 < NN)
            *reinterpret_cast<float2*>(&g_qhat[(size_t)r1 * D + col]) =
                make_float2(acc[nt][2], acc[nt][3]);
    }
}

// ================ gemm2 + bias + LayerNorm: 64x128 tile, 256 thr ===========
#define SMEM_G2_BYTES ((64 + 128 + 128) * 36 * 4)   // 46080

__global__ __launch_bounds__(256, 4) void gemm_ln_kernel(const float* __restrict__ bo,
                                                         const float* __restrict__ gamma,
                                                         const float* __restrict__ beta,
                                                         float* __restrict__ out) {
    extern __shared__ float sm[];
    float* As = sm;
    float* Bh = sm + 64 * 36;
    float* Bl = sm + (64 + 128) * 36;
    int t  = threadIdx.x;
    int rb = blockIdx.x * 64;
    int w = t >> 5, lane = t & 31;
    int wm = w >> 1, wn = w & 1;
    int qid = lane >> 2, tq = lane & 3;
    int ra = wm * 16 + qid;
    float acc[8][4];
#pragma unroll
    for (int nt = 0; nt < 8; nt++)
        acc[nt][0] = acc[nt][1] = acc[nt][2] = acc[nt][3] = 0.f;
    const float4* A4  = reinterpret_cast<const float4*>(g_agg);
    const float4* BH4 = reinterpret_cast<const float4*>(g_W2H);
    const float4* BL4 = reinterpret_cast<const float4*>(g_W2L);
    for (int kt = 0; kt < 4; kt++) {
        __syncthreads();
#pragma unroll
        for (int i = 0; i < 2; i++) {
            int lin = i * 256 + t;
            int r = lin >> 3, c4 = lin & 7;
            float4 v = make_float4(0.f, 0.f, 0.f, 0.f);
            if (rb + r < NN) v = A4[(size_t)(rb + r) * 32 + kt * 8 + c4];
            *reinterpret_cast<float4*>(&As[r * 36 + c4 * 4]) = v;
        }
#pragma unroll
        for (int i = 0; i < 4; i++) {
            int lin = i * 256 + t;
            int r = lin >> 3, c4 = lin & 7;
            *reinterpret_cast<float4*>(&Bh[r * 36 + c4 * 4]) =
                BH4[r * 32 + kt * 8 + c4];
            *reinterpret_cast<float4*>(&Bl[r * 36 + c4 * 4]) =
                BL4[r * 32 + kt * 8 + c4];
        }
        __syncthreads();
#pragma unroll
        for (int k8 = 0; k8 < 4; k8++) {
            int k0 = k8 * 8;
            float a0f = As[ra * 36 + k0 + tq];
            float a1f = As[(ra + 8) * 36 + k0 + tq];
            float a2f = As[ra * 36 + k0 + 4 + tq];
            float a3f = As[(ra + 8) * 36 + k0 + 4 + tq];
            unsigned ah0 = tf32_hi(a0f), ah1 = tf32_hi(a1f);
            unsigned ah2 = tf32_hi(a2f), ah3 = tf32_hi(a3f);
            unsigned al0 = tf32_hi(a0f - __uint_as_float(ah0));
            unsigned al1 = tf32_hi(a1f - __uint_as_float(ah1));
            unsigned al2 = tf32_hi(a2f - __uint_as_float(ah2));
            unsigned al3 = tf32_hi(a3f - __uint_as_float(ah3));
#pragma unroll
            for (int nt = 0; nt < 8; nt++) {
                int nb = (wn * 64 + nt * 8 + qid) * 36 + k0 + tq;
                unsigned bh0 = __float_as_uint(Bh[nb]);
                unsigned bh1 = __float_as_uint(Bh[nb + 4]);
                unsigned bl0 = __float_as_uint(Bl[nb]);
                unsigned bl1 = __float_as_uint(Bl[nb + 4]);
                MMA_TF32(acc[nt], al0, al1, al2, al3, bh0, bh1);
                MMA_TF32(acc[nt], ah0, ah1, ah2, ah3, bl0, bl1);
                MMA_TF32(acc[nt], ah0, ah1, ah2, ah3, bh0, bh1);
            }
        }
    }
#pragma unroll
    for (int nt = 0; nt < 8; nt++) {
        int col = wn * 64 + nt * 8 + 2 * tq;
        float2 b2 = *reinterpret_cast<const float2*>(&bo[col]);
        acc[nt][0] += b2.x; acc[nt][1] += b2.y;
        acc[nt][2] += b2.x; acc[nt][3] += b2.y;
    }
    float s0 = 0.f, s1 = 0.f, q0 = 0.f, q1 = 0.f;
#pragma unroll
    for (int nt = 0; nt < 8; nt++) {
        s0 += acc[nt][0] + acc[nt][1];
        s1 += acc[nt][2] + acc[nt][3];
        q0 += acc[nt][0] * acc[nt][0] + acc[nt][1] * acc[nt][1];
        q1 += acc[nt][2] * acc[nt][2] + acc[nt][3] * acc[nt][3];
    }
#pragma unroll
    for (int o = 1; o <= 2; o <<= 1) {
        s0 += __shfl_xor_sync(0xffffffffu, s0, o);
        s1 += __shfl_xor_sync(0xffffffffu, s1, o);
        q0 += __shfl_xor_sync(0xffffffffu, q0, o);
        q1 += __shfl_xor_sync(0xffffffffu, q1, o);
    }
    float* red_s = As;
    float* red_q = As + 128;
    __syncthreads();
    if (tq == 0) {
        int row0 = wm * 16 + qid;
        red_s[wn * 64 + row0]     = s0;
        red_s[wn * 64 + row0 + 8] = s1;
        red_q[wn * 64 + row0]     = q0;
        red_q[wn * 64 + row0 + 8] = q1;
    }
    __syncthreads();
    int row0 = wm * 16 + qid, row1 = row0 + 8;
    float st0 = red_s[row0] + red_s[64 + row0];
    float st1 = red_s[row1] + red_s[64 + row1];
    float qt0 = red_q[row0] + red_q[64 + row0];
    float qt1 = red_q[row1] + red_q[64 + row1];
    float mu0 = st0 * (1.f / 128.f), mu1 = st1 * (1.f / 128.f);
    float var0 = qt0 * (1.f / 128.f) - mu0 * mu0;
    float var1 = qt1 * (1.f / 128.f) - mu1 * mu1;
    float rs0 = rsqrtf(var0 + 1e-5f);
    float rs1 = rsqrtf(var1 + 1e-5f);

    int r0 = rb + ra, r1 = r0 + 8;
#pragma unroll
    for (int nt = 0; nt < 8; nt++) {
        int col = wn * 64 + nt * 8 + 2 * tq;
        float2 g2  = *reinterpret_cast<const float2*>(&gamma[col]);
        float2 be2 = *reinterpret_cast<const float2*>(&beta[col]);
        if (r0 < NN)
            *reinterpret_cast<float2*>(&out[(size_t)r0 * D + col]) =
                make_float2((acc[nt][0] - mu0) * rs0 * g2.x + be2.x,
                            (acc[nt][1] - mu0) * rs0 * g2.y + be2.y);
        if (r1 < NN)
            *reinterpret_cast<float2*>(&out[(size_t)r1 * D + col]) =
                make_float2((acc[nt][2] - mu1) * rs1 * g2.x + be2.x,
                            (acc[nt][3] - mu1) * rs1 * g2.y + be2.y);
    }
}

// ---------------- scores: warp per 8 edges; CSR-ordered exp + eids ----------------
__global__ void scores_kernel(const float* __restrict__ key_edge,
                              const int* __restrict__ tgt) {
    int w = (blockIdx.x * blockDim.x + threadIdx.x) >> 5;
    int e0 = w * 8;
    if (e0 >= NE) return;
    int lane = threadIdx.x & 31;

    int4 ta = *reinterpret_cast<const int4*>(tgt + e0);
    int4 tb = *reinterpret_cast<const int4*>(tgt + e0 + 4);
    int t[8] = {ta.x, ta.y, ta.z, ta.w, tb.x, tb.y, tb.z, tb.w};

    const float4* K4 = reinterpret_cast<const float4*>(key_edge);
    const float4* Q4 = reinterpret_cast<const float4*>(g_qhat);

    float4 kv[8], qv[8];
#pragma unroll
    for (int j = 0; j < 8; j++) kv[j] = __ldcs(&K4[(size_t)(e0 + j) * 32 + lane]);
#pragma unroll
    for (int j = 0; j < 8; j++) qv[j] = Q4[(size_t)t[j] * 32 + lane];

    float d[8];
#pragma unroll
    for (int j = 0; j < 8; j++)
        d[j] = kv[j].x * qv[j].x + kv[j].y * qv[j].y + kv[j].z * qv[j].z + kv[j].w * qv[j].w;
#pragma unroll
    for (int o = 16; o; o >>= 1) {
#pragma unroll
        for (int j = 0; j < 8; j++) d[j] += __shfl_xor_sync(0xffffffffu, d[j], o);
    }
    if (lane < 8) {
        float ds; int ts;
#pragma unroll
        for (int j = 0; j < 8; j++) if (lane == j) { ds = d[j]; ts = t[j]; }
        float sc = ds * 0.08838834764831845f;   // 128^-0.5
        float ex = expf(sc);                    // scores ~ N(0,1): safe without max-shift
        int p = g_off[ts] + atomicAdd(&g_cur[ts], 1);
        g_eids[p] = e0 + lane;
        g_exp[p]  = ex;
    }
}

// ---------------- node: single-pass aggregation + late normalize ----------------
__global__ void node_kernel(const float* __restrict__ value,
                            float* __restrict__ attn_out) {
    int n = (blockIdx.x << 3) + (threadIdx.x >> 5);
    if (n >= NN) return;
    int lane = threadIdx.x & 31;
    int s0 = g_off[n], s1 = g_off[n + 1];

    const float4* V4 = reinterpret_cast<const float4*>(value);
    float ss = 0.f;
    float4 acc = make_float4(0.f, 0.f, 0.f, 0.f);

    int i = s0;
    for (; i + 8 <= s1; i += 8) {
        int   e[8];
        float wgt[8];
        float4 v[8];
#pragma unroll
        for (int j = 0; j < 8; j++) e[j] = g_eids[i + j];
#pragma unroll
        for (int j = 0; j < 8; j++) wgt[j] = g_exp[i + j];
#pragma unroll
        for (int j = 0; j < 8; j++) v[j] = __ldcs(&V4[(size_t)e[j] * 32 + lane]);
#pragma unroll
        for (int j = 0; j < 8; j++) {
            ss += wgt[j];
            acc.x = fmaf(wgt[j], v[j].x, acc.x);
            acc.y = fmaf(wgt[j], v[j].y, acc.y);
            acc.z = fmaf(wgt[j], v[j].z, acc.z);
            acc.w = fmaf(wgt[j], v[j].w, acc.w);
        }
    }
    for (; i < s1; i++) {
        int e = g_eids[i];
        float w = g_exp[i];
        ss += w;
        float4 v = __ldcs(&V4[(size_t)e * 32 + lane]);
        acc.x = fmaf(w, v.x, acc.x); acc.y = fmaf(w, v.y, acc.y);
        acc.z = fmaf(w, v.z, acc.z); acc.w = fmaf(w, v.w, acc.w);
    }
    float inv = 1.f / (ss + 1e-12f);
    acc.x *= inv; acc.y *= inv; acc.z *= inv; acc.w *= inv;
    reinterpret_cast<float4*>(g_agg)[(size_t)n * 32 + lane] = acc;

    if (attn_out) {
        for (int k = s0 + lane; k < s1; k += 32)
            attn_out[g_eids[k]] = g_exp[k] * inv;
    }
}

// ---------------- launch (two-stream DAG) ----------------
extern "C" void kernel_launch(void* const* d_in, const int* in_sizes, int n_in,
                              void* d_out, int out_size) {
    const float* qn    = (const float*)d_in[0];
    const float* ke    = (const float*)d_in[1];
    const float* ve    = (const float*)d_in[2];
    const int*   ei    = (const int*)  d_in[3];
    const float* Wq    = (const float*)d_in[4];
    const float* Wk    = (const float*)d_in[5];
    const float* Wv    = (const float*)d_in[6];
    const float* Wo    = (const float*)d_in[7];
    const float* bo    = (const float*)d_in[8];
    const float* gamma = (const float*)d_in[9];
    const float* beta  = (const float*)d_in[10];

    const int* tgt = ei + NE;
    float* out = (float*)d_out;
    float* attn = (out_size >= NN * D + NE) ? (out + NN * D) : nullptr;

    static int inited = 0;
    static cudaStream_t sB;
    static cudaEvent_t evFork, evJoin;
    if (!inited) {
        cudaFuncSetAttribute(gemm_qhat_kernel,
                             cudaFuncAttributeMaxDynamicSharedMemorySize, SMEM_G1_BYTES);
        cudaFuncSetAttribute(gemm_ln_kernel,
                             cudaFuncAttributeMaxDynamicSharedMemorySize, SMEM_G2_BYTES);
        cudaStreamCreateWithFlags(&sB, cudaStreamNonBlocking);
        cudaEventCreateWithFlags(&evFork, cudaEventDisableTiming);
        cudaEventCreateWithFlags(&evJoin, cudaEventDisableTiming);
        inited = 1;
    }

    // fork: B-chain (CSR build) runs under the A-chain's shadow
    cudaEventRecord(evFork, 0);
    cudaStreamWaitEvent(sB, evFork, 0);
    zero_kernel<<<20, 1024, 0, sB>>>();
    deg_kernel<<<625, 256, 0, sB>>>(tgt);
    scan_kernel<<<1, 1024, 0, sB>>>();
    cudaEventRecord(evJoin, sB);

    // A-chain: weights -> gemm1 (64x64 tiles, 2 col-halves per 64 rows)
    transpose_kernel<<<16, 1024>>>(Wo);
    combine_kernel<<<4096, 256>>>(Wq, Wk, Wv);
    gemm_qhat_kernel<<<((NN + 63) / 64) * 2, 128, SMEM_G1_BYTES>>>(qn);

    // join, then the dependent chain
    cudaStreamWaitEvent(0, evJoin, 0);
    scores_kernel<<<(NE / 8 + 7) / 8, 256>>>(ke, tgt);
    node_kernel<<<(NN + 7) / 8, 256>>>(ve, attn);
    gemm_ln_kernel<<<(NN + 63) / 64, 256, SMEM_G2_BYTES>>>(bo, gamma, beta, out);
}

// round 17
// speedup vs baseline: 1.0732x; 1.0623x over previous
#include <cuda_runtime.h>
#include <math.h>

#define NN 20000
#define NE 640000
#define D  128

// ---------------- static device scratch ----------------
__device__ float g_qhat[NN * D];
__device__ float g_agg[NN * D];
__device__ float g_exp[NE];
__device__ int   g_eids[NE];
__device__ int   g_deg[NN];
__device__ int   g_off[NN + 1];
__device__ int   g_cur[NN];
__device__ float g_WoT[D * D];       // Wo^T
// tf32 hi/lo split of combined weights, n-major [n*128 + k]
__device__ float g_WcH[D * D], g_WcL[D * D];
__device__ float g_W2H[D * D], g_W2L[D * D];

// ---------------- tf32 helpers ----------------
__device__ __forceinline__ unsigned tf32_hi(float a) {
    unsigned h;
    asm("cvt.rna.tf32.f32 %0, %1;" : "=r"(h) : "f"(a));
    return h;
}

#define MMA_TF32(c, a0, a1, a2, a3, b0, b1)                                    \
    asm("mma.sync.aligned.m16n8k8.row.col.f32.tf32.tf32.f32 "                  \
        "{%0,%1,%2,%3}, {%4,%5,%6,%7}, {%8,%9}, {%0,%1,%2,%3};"                \
        : "+f"(c[0]), "+f"(c[1]), "+f"(c[2]), "+f"(c[3])                       \
        : "r"(a0), "r"(a1), "r"(a2), "r"(a3), "r"(b0), "r"(b1))

// ---------------- B-chain: zero counters ----------------
__global__ void zero_kernel() {
    int i = blockIdx.x * 1024 + threadIdx.x;
    if (i < NN) { g_deg[i] = 0; g_cur[i] = 0; }
}

// ---------------- B-chain: degree histogram ----------------
__global__ void deg_kernel(const int* __restrict__ tgt) {
    int i = (blockIdx.x * 256 + threadIdx.x) * 4;
    if (i >= NE) return;
    int4 t = *reinterpret_cast<const int4*>(tgt + i);
    atomicAdd(&g_deg[t.x], 1);
    atomicAdd(&g_deg[t.y], 1);
    atomicAdd(&g_deg[t.z], 1);
    atomicAdd(&g_deg[t.w], 1);
}

// ---------------- B-chain: single-block scan ----------------
__global__ void scan_kernel() {
    const int PER = (NN + 1023) / 1024;          // 20
    int t = threadIdx.x;
    int lane = t & 31, wid = t >> 5;
    int base = t * PER;

    int local[PER];
    int s = 0;
#pragma unroll
    for (int j = 0; j < PER; j++) {
        int idx = base + j;
        int v = (idx < NN) ? g_deg[idx] : 0;
        local[j] = s;
        s += v;
    }
    int incl = s;
#pragma unroll
    for (int o = 1; o < 32; o <<= 1) {
        int u = __shfl_up_sync(0xffffffffu, incl, o);
        if (lane >= o) incl += u;
    }
    __shared__ int wsum[32];
    if (lane == 31) wsum[wid] = incl;
    __syncthreads();
    if (wid == 0) {
        int v = wsum[lane];
        int wv = v;
#pragma unroll
        for (int o = 1; o < 32; o <<= 1) {
            int u = __shfl_up_sync(0xffffffffu, wv, o);
            if (lane >= o) wv += u;
        }
        wsum[lane] = wv - v;
    }
    __syncthreads();
    int excl = incl - s + wsum[wid];
#pragma unroll
    for (int j = 0; j < PER; j++) {
        int idx = base + j;
        if (idx < NN) g_off[idx] = excl + local[j];
    }
    if (t == 1023) g_off[NN] = excl + s;
}

// ---------------- B-chain: transpose Wo (only needed for W2 / gemm_ln) -------
__global__ void transpose_kernel(const float* __restrict__ Wo) {
    __shared__ float tile[32][33];
    int ti = blockIdx.x;
    int bx = ti & 3, by = ti >> 2;
    int tx = threadIdx.x & 31, ty = threadIdx.x >> 5;
    tile[ty][tx] = Wo[(by * 32 + ty) * D + bx * 32 + tx];
    __syncthreads();
    g_WoT[(bx * 32 + ty) * D + by * 32 + tx] = tile[tx][ty];
}

// ---------------- A-chain: combine Wc = Wq @ Wk^T (tf32 split, n-major) ------
__global__ void combine_wc_kernel(const float* __restrict__ Wq,
                                  const float* __restrict__ Wk) {
    int w = (blockIdx.x * 256 + threadIdx.x) >> 5;   // 0..16383
    int lane = threadIdx.x & 31;
    int a = (w >> 7) & 127;   // k index
    int b = w & 127;          // n index
    float4 x = reinterpret_cast<const float4*>(Wq)[a * 32 + lane];
    float4 y = reinterpret_cast<const float4*>(Wk)[b * 32 + lane];
    float c = x.x * y.x + x.y * y.y + x.z * y.z + x.w * y.w;
#pragma unroll
    for (int o = 16; o; o >>= 1) c += __shfl_xor_sync(0xffffffffu, c, o);
    if (lane == 0) {
        unsigned h = tf32_hi(c);
        float lo = c - __uint_as_float(h);
        g_WcH[b * D + a] = __uint_as_float(h);
        g_WcL[b * D + a] = __uint_as_float(tf32_hi(lo));
    }
}

// ---------------- B-chain: combine W2 = Wv @ Wo (tf32 split, n-major) --------
__global__ void combine_w2_kernel(const float* __restrict__ Wv) {
    int w = (blockIdx.x * 256 + threadIdx.x) >> 5;   // 0..16383
    int lane = threadIdx.x & 31;
    int a = (w >> 7) & 127;
    int b = w & 127;
    float4 x = reinterpret_cast<const float4*>(Wv)[a * 32 + lane];
    float4 y = reinterpret_cast<const float4*>(g_WoT)[b * 32 + lane];
    float c = x.x * y.x + x.y * y.y + x.z * y.z + x.w * y.w;
#pragma unroll
    for (int o = 16; o; o >>= 1) c += __shfl_xor_sync(0xffffffffu, c, o);
    if (lane == 0) {
        unsigned h = tf32_hi(c);
        float lo = c - __uint_as_float(h);
        g_W2H[b * D + a] = __uint_as_float(h);
        g_W2L[b * D + a] = __uint_as_float(tf32_hi(lo));
    }
}

// ================ gemm1: 64x64 tile, 128 thr, 4 warps (high occupancy) ======
#define SMEM_G1_BYTES (3 * 64 * 36 * 4)   // 27648

__global__ __launch_bounds__(128, 8) void gemm_qhat_kernel(const float* __restrict__ A) {
    extern __shared__ float sm[];
    float* As = sm;
    float* Bh = sm + 64 * 36;
    float* Bl = sm + 2 * 64 * 36;
    int t  = threadIdx.x;
    int rb = (blockIdx.x >> 1) * 64;
    int cb = blockIdx.x & 1;
    int w = t >> 5, lane = t & 31;
    int qid = lane >> 2, tq = lane & 3;
    int ra = w * 16 + qid;
    float acc[8][4];
#pragma unroll
    for (int nt = 0; nt < 8; nt++)
        acc[nt][0] = acc[nt][1] = acc[nt][2] = acc[nt][3] = 0.f;
    const float4* A4  = reinterpret_cast<const float4*>(A);
    const float4* BH4 = reinterpret_cast<const float4*>(g_WcH);
    const float4* BL4 = reinterpret_cast<const float4*>(g_WcL);
    for (int kt = 0; kt < 4; kt++) {
        __syncthreads();
#pragma unroll
        for (int i = 0; i < 4; i++) {
            int lin = i * 128 + t;
            int r = lin >> 3, c4 = lin & 7;
            float4 v = make_float4(0.f, 0.f, 0.f, 0.f);
            if (rb + r < NN) v = A4[(size_t)(rb + r) * 32 + kt * 8 + c4];
            *reinterpret_cast<float4*>(&As[r * 36 + c4 * 4]) = v;
            *reinterpret_cast<float4*>(&Bh[r * 36 + c4 * 4]) =
                BH4[(cb * 64 + r) * 32 + kt * 8 + c4];
            *reinterpret_cast<float4*>(&Bl[r * 36 + c4 * 4]) =
                BL4[(cb * 64 + r) * 32 + kt * 8 + c4];
        }
        __syncthreads();
#pragma unroll
        for (int k8 = 0; k8 < 4; k8++) {
            int k0 = k8 * 8;
            float a0f = As[ra * 36 + k0 + tq];
            float a1f = As[(ra + 8) * 36 + k0 + tq];
            float a2f = As[ra * 36 + k0 + 4 + tq];
            float a3f = As[(ra + 8) * 36 + k0 + 4 + tq];
            unsigned ah0 = tf32_hi(a0f), ah1 = tf32_hi(a1f);
            unsigned ah2 = tf32_hi(a2f), ah3 = tf32_hi(a3f);
            unsigned al0 = tf32_hi(a0f - __uint_as_float(ah0));
            unsigned al1 = tf32_hi(a1f - __uint_as_float(ah1));
            unsigned al2 = tf32_hi(a2f - __uint_as_float(ah2));
            unsigned al3 = tf32_hi(a3f - __uint_as_float(ah3));
#pragma unroll
            for (int nt = 0; nt < 8; nt++) {
                int nb = (nt * 8 + qid) * 36 + k0 + tq;
                unsigned bh0 = __float_as_uint(Bh[nb]);
                unsigned bh1 = __float_as_uint(Bh[nb + 4]);
                unsigned bl0 = __float_as_uint(Bl[nb]);
                unsigned bl1 = __float_as_uint(Bl[nb + 4]);
                MMA_TF32(acc[nt], al0, al1, al2, al3, bh0, bh1);
                MMA_TF32(acc[nt], ah0, ah1, ah2, ah3, bl0, bl1);
                MMA_TF32(acc[nt], ah0, ah1, ah2, ah3, bh0, bh1);
            }
        }
    }
    int r0 = rb + ra, r1 = r0 + 8;
#pragma unroll
    for (int nt = 0; nt < 8; nt++) {
        int col = cb * 64 + nt * 8 + 2 * tq;
        if (r0 < NN)
            *reinterpret_cast<float2*>(&g_qhat[(size_t)r0 * D + col]) =
                make_float2(acc[nt][0], acc[nt][1]);
        if (r1 < NN)
            *reinterpret_cast<float2*>(&g_qhat[(size_t)r1 * D + col]) =
                make_float2(acc[nt][2], acc[nt][3]);
    }
}

// ================ gemm2 + bias + LayerNorm: 64x128 tile, 256 thr ===========
#define SMEM_G2_BYTES ((64 + 128 + 128) * 36 * 4)   // 46080

__global__ __launch_bounds__(256, 4) void gemm_ln_kernel(const float* __restrict__ bo,
                                                         const float* __restrict__ gamma,
                                                         const float* __restrict__ beta,
                                                         float* __restrict__ out) {
    extern __shared__ float sm[];
    float* As = sm;
    float* Bh = sm + 64 * 36;
    float* Bl = sm + (64 + 128) * 36;
    int t  = threadIdx.x;
    int rb = blockIdx.x * 64;
    int w = t >> 5, lane = t & 31;
    int wm = w >> 1, wn = w & 1;
    int qid = lane >> 2, tq = lane & 3;
    int ra = wm * 16 + qid;
    float acc[8][4];
#pragma unroll
    for (int nt = 0; nt < 8; nt++)
        acc[nt][0] = acc[nt][1] = acc[nt][2] = acc[nt][3] = 0.f;
    const float4* A4  = reinterpret_cast<const float4*>(g_agg);
    const float4* BH4 = reinterpret_cast<const float4*>(g_W2H);
    const float4* BL4 = reinterpret_cast<const float4*>(g_W2L);
    for (int kt = 0; kt < 4; kt++) {
        __syncthreads();
#pragma unroll
        for (int i = 0; i < 2; i++) {
            int lin = i * 256 + t;
            int r = lin >> 3, c4 = lin & 7;
            float4 v = make_float4(0.f, 0.f, 0.f, 0.f);
            if (rb + r < NN) v = A4[(size_t)(rb + r) * 32 + kt * 8 + c4];
            *reinterpret_cast<float4*>(&As[r * 36 + c4 * 4]) = v;
        }
#pragma unroll
        for (int i = 0; i < 4; i++) {
            int lin = i * 256 + t;
            int r = lin >> 3, c4 = lin & 7;
            *reinterpret_cast<float4*>(&Bh[r * 36 + c4 * 4]) =
                BH4[r * 32 + kt * 8 + c4];
            *reinterpret_cast<float4*>(&Bl[r * 36 + c4 * 4]) =
                BL4[r * 32 + kt * 8 + c4];
        }
        __syncthreads();
#pragma unroll
        for (int k8 = 0; k8 < 4; k8++) {
            int k0 = k8 * 8;
            float a0f = As[ra * 36 + k0 + tq];
            float a1f = As[(ra + 8) * 36 + k0 + tq];
            float a2f = As[ra * 36 + k0 + 4 + tq];
            float a3f = As[(ra + 8) * 36 + k0 + 4 + tq];
            unsigned ah0 = tf32_hi(a0f), ah1 = tf32_hi(a1f);
            unsigned ah2 = tf32_hi(a2f), ah3 = tf32_hi(a3f);
            unsigned al0 = tf32_hi(a0f - __uint_as_float(ah0));
            unsigned al1 = tf32_hi(a1f - __uint_as_float(ah1));
            unsigned al2 = tf32_hi(a2f - __uint_as_float(ah2));
            unsigned al3 = tf32_hi(a3f - __uint_as_float(ah3));
#pragma unroll
            for (int nt = 0; nt < 8; nt++) {
                int nb = (wn * 64 + nt * 8 + qid) * 36 + k0 + tq;
                unsigned bh0 = __float_as_uint(Bh[nb]);
                unsigned bh1 = __float_as_uint(Bh[nb + 4]);
                unsigned bl0 = __float_as_uint(Bl[nb]);
                unsigned bl1 = __float_as_uint(Bl[nb + 4]);
                MMA_TF32(acc[nt], al0, al1, al2, al3, bh0, bh1);
                MMA_TF32(acc[nt], ah0, ah1, ah2, ah3, bl0, bl1);
                MMA_TF32(acc[nt], ah0, ah1, ah2, ah3, bh0, bh1);
            }
        }
    }
#pragma unroll
    for (int nt = 0; nt < 8; nt++) {
        int col = wn * 64 + nt * 8 + 2 * tq;
        float2 b2 = *reinterpret_cast<const float2*>(&bo[col]);
        acc[nt][0] += b2.x; acc[nt][1] += b2.y;
        acc[nt][2] += b2.x; acc[nt][3] += b2.y;
    }
    float s0 = 0.f, s1 = 0.f, q0 = 0.f, q1 = 0.f;
#pragma unroll
    for (int nt = 0; nt < 8; nt++) {
        s0 += acc[nt][0] + acc[nt][1];
        s1 += acc[nt][2] + acc[nt][3];
        q0 += acc[nt][0] * acc[nt][0] + acc[nt][1] * acc[nt][1];
        q1 += acc[nt][2] * acc[nt][2] + acc[nt][3] * acc[nt][3];
    }
#pragma unroll
    for (int o = 1; o <= 2; o <<= 1) {
        s0 += __shfl_xor_sync(0xffffffffu, s0, o);
        s1 += __shfl_xor_sync(0xffffffffu, s1, o);
        q0 += __shfl_xor_sync(0xffffffffu, q0, o);
        q1 += __shfl_xor_sync(0xffffffffu, q1, o);
    }
    float* red_s = As;
    float* red_q = As + 128;
    __syncthreads();
    if (tq == 0) {
        int row0 = wm * 16 + qid;
        red_s[wn * 64 + row0]     = s0;
        red_s[wn * 64 + row0 + 8] = s1;
        red_q[wn * 64 + row0]     = q0;
        red_q[wn * 64 + row0 + 8] = q1;
    }
    __syncthreads();
    int row0 = wm * 16 + qid, row1 = row0 + 8;
    float st0 = red_s[row0] + red_s[64 + row0];
    float st1 = red_s[row1] + red_s[64 + row1];
    float qt0 = red_q[row0] + red_q[64 + row0];
    float qt1 = red_q[row1] + red_q[64 + row1];
    float mu0 = st0 * (1.f / 128.f), mu1 = st1 * (1.f / 128.f);
    float var0 = qt0 * (1.f / 128.f) - mu0 * mu0;
    float var1 = qt1 * (1.f / 128.f) - mu1 * mu1;
    float rs0 = rsqrtf(var0 + 1e-5f);
    float rs1 = rsqrtf(var1 + 1e-5f);

    int r0 = rb + ra, r1 = r0 + 8;
#pragma unroll
    for (int nt = 0; nt < 8; nt++) {
        int col = wn * 64 + nt * 8 + 2 * tq;
        float2 g2  = *reinterpret_cast<const float2*>(&gamma[col]);
        float2 be2 = *reinterpret_cast<const float2*>(&beta[col]);
        if (r0 < NN)
            *reinterpret_cast<float2*>(&out[(size_t)r0 * D + col]) =
                make_float2((acc[nt][0] - mu0) * rs0 * g2.x + be2.x,
                            (acc[nt][1] - mu0) * rs0 * g2.y + be2.y);
        if (r1 < NN)
            *reinterpret_cast<float2*>(&out[(size_t)r1 * D + col]) =
                make_float2((acc[nt][2] - mu1) * rs1 * g2.x + be2.x,
                            (acc[nt][3] - mu1) * rs1 * g2.y + be2.y);
    }
}

// ---------------- scores: warp per 8 edges; CSR-ordered exp + eids ----------------
__global__ void scores_kernel(const float* __restrict__ key_edge,
                              const int* __restrict__ tgt) {
    int w = (blockIdx.x * blockDim.x + threadIdx.x) >> 5;
    int e0 = w * 8;
    if (e0 >= NE) return;
    int lane = threadIdx.x & 31;

    int4 ta = *reinterpret_cast<const int4*>(tgt + e0);
    int4 tb = *reinterpret_cast<const int4*>(tgt + e0 + 4);
    int t[8] = {ta.x, ta.y, ta.z, ta.w, tb.x, tb.y, tb.z, tb.w};

    const float4* K4 = reinterpret_cast<const float4*>(key_edge);
    const float4* Q4 = reinterpret_cast<const float4*>(g_qhat);

    float4 kv[8], qv[8];
#pragma unroll
    for (int j = 0; j < 8; j++) kv[j] = __ldcs(&K4[(size_t)(e0 + j) * 32 + lane]);
#pragma unroll
    for (int j = 0; j < 8; j++) qv[j] = Q4[(size_t)t[j] * 32 + lane];

    float d[8];
#pragma unroll
    for (int j = 0; j < 8; j++)
        d[j] = kv[j].x * qv[j].x + kv[j].y * qv[j].y + kv[j].z * qv[j].z + kv[j].w * qv[j].w;
#pragma unroll
    for (int o = 16; o; o >>= 1) {
#pragma unroll
        for (int j = 0; j < 8; j++) d[j] += __shfl_xor_sync(0xffffffffu, d[j], o);
    }
    if (lane < 8) {
        float ds; int ts;
#pragma unroll
        for (int j = 0; j < 8; j++) if (lane == j) { ds = d[j]; ts = t[j]; }
        float sc = ds * 0.08838834764831845f;   // 128^-0.5
        float ex = expf(sc);                    // scores ~ N(0,1): safe without max-shift
        int p = g_off[ts] + atomicAdd(&g_cur[ts], 1);
        g_eids[p] = e0 + lane;
        g_exp[p]  = ex;
    }
}

// ---------------- node: single-pass aggregation + late normalize ----------------
__global__ void node_kernel(const float* __restrict__ value,
                            float* __restrict__ attn_out) {
    int n = (blockIdx.x << 3) + (threadIdx.x >> 5);
    if (n >= NN) return;
    int lane = threadIdx.x & 31;
    int s0 = g_off[n], s1 = g_off[n + 1];

    const float4* V4 = reinterpret_cast<const float4*>(value);
    float ss = 0.f;
    float4 acc = make_float4(0.f, 0.f, 0.f, 0.f);

    int i = s0;
    for (; i + 8 <= s1; i += 8) {
        int   e[8];
        float wgt[8];
        float4 v[8];
#pragma unroll
        for (int j = 0; j < 8; j++) e[j] = g_eids[i + j];
#pragma unroll
        for (int j = 0; j < 8; j++) wgt[j] = g_exp[i + j];
#pragma unroll
        for (int j = 0; j < 8; j++) v[j] = __ldcs(&V4[(size_t)e[j] * 32 + lane]);
#pragma unroll
        for (int j = 0; j < 8; j++) {
            ss += wgt[j];
            acc.x = fmaf(wgt[j], v[j].x, acc.x);
            acc.y = fmaf(wgt[j], v[j].y, acc.y);
            acc.z = fmaf(wgt[j], v[j].z, acc.z);
            acc.w = fmaf(wgt[j], v[j].w, acc.w);
        }
    }
    for (; i < s1; i++) {
        int e = g_eids[i];
        float w = g_exp[i];
        ss += w;
        float4 v = __ldcs(&V4[(size_t)e * 32 + lane]);
        acc.x = fmaf(w, v.x, acc.x); acc.y = fmaf(w, v.y, acc.y);
        acc.z = fmaf(w, v.z, acc.z); acc.w = fmaf(w, v.w, acc.w);
    }
    float inv = 1.f / (ss + 1e-12f);
    acc.x *= inv; acc.y *= inv; acc.z *= inv; acc.w *= inv;
    reinterpret_cast<float4*>(g_agg)[(size_t)n * 32 + lane] = acc;

    if (attn_out) {
        for (int k = s0 + lane; k < s1; k += 32)
            attn_out[g_eids[k]] = g_exp[k] * inv;
    }
}

// ---------------- launch (two-stream DAG, lazy W2 chain) ----------------
extern "C" void kernel_launch(void* const* d_in, const int* in_sizes, int n_in,
                              void* d_out, int out_size) {
    const float* qn    = (const float*)d_in[0];
    const float* ke    = (const float*)d_in[1];
    const float* ve    = (const float*)d_in[2];
    const int*   ei    = (const int*)  d_in[3];
    const float* Wq    = (const float*)d_in[4];
    const float* Wk    = (const float*)d_in[5];
    const float* Wv    = (const float*)d_in[6];
    const float* Wo    = (const float*)d_in[7];
    const float* bo    = (const float*)d_in[8];
    const float* gamma = (const float*)d_in[9];
    const float* beta  = (const float*)d_in[10];

    const int* tgt = ei + NE;
    float* out = (float*)d_out;
    float* attn = (out_size >= NN * D + NE) ? (out + NN * D) : nullptr;

    static int inited = 0;
    static cudaStream_t sB;
    static cudaEvent_t evFork, evJoin, evW2;
    if (!inited) {
        cudaFuncSetAttribute(gemm_qhat_kernel,
                             cudaFuncAttributeMaxDynamicSharedMemorySize, SMEM_G1_BYTES);
        cudaFuncSetAttribute(gemm_ln_kernel,
                             cudaFuncAttributeMaxDynamicSharedMemorySize, SMEM_G2_BYTES);
        cudaStreamCreateWithFlags(&sB, cudaStreamNonBlocking);
        cudaEventCreateWithFlags(&evFork, cudaEventDisableTiming);
        cudaEventCreateWithFlags(&evJoin, cudaEventDisableTiming);
        cudaEventCreateWithFlags(&evW2, cudaEventDisableTiming);
        inited = 1;
    }

    // fork: B-chain (CSR build + W2 weight chain) under the A-chain's shadow
    cudaEventRecord(evFork, 0);
    cudaStreamWaitEvent(sB, evFork, 0);
    zero_kernel<<<20, 1024, 0, sB>>>();
    deg_kernel<<<625, 256, 0, sB>>>(tgt);
    scan_kernel<<<1, 1024, 0, sB>>>();
    cudaEventRecord(evJoin, sB);
    transpose_kernel<<<16, 1024, 0, sB>>>(Wo);
    combine_w2_kernel<<<2048, 256, 0, sB>>>(Wv);
    cudaEventRecord(evW2, sB);

    // A-chain: Wc -> gemm1 (transpose/W2 are OFF the critical path)
    combine_wc_kernel<<<2048, 256>>>(Wq, Wk);
    gemm_qhat_kernel<<<((NN + 63) / 64) * 2, 128, SMEM_G1_BYTES>>>(qn);

    // join CSR, then the dependent chain
    cudaStreamWaitEvent(0, evJoin, 0);
    scores_kernel<<<(NE / 8 + 7) / 8, 256>>>(ke, tgt);
    node_kernel<<<(NN + 7) / 8, 256>>>(ve, attn);
    cudaStreamWaitEvent(0, evW2, 0);
    gemm_ln_kernel<<<(NN + 63) / 64, 256, SMEM_G2_BYTES>>>(bo, gamma, beta, out);
}